// round 15
// baseline (speedup 1.0000x reference)
#include <cuda_runtime.h>
#include <cuda_bf16.h>
#include <cstdint>

#define NN   50000
#define EE   800000
#define ET   (EE + NN)        // edges incl. self loops = 850000
#define FD   128
#define HH   2
#define GG   64
#define OUTD 10
#define NTILE ((NN + 127) / 128)   // 391 M-tiles
#define SBLK ((NN + 1023) / 1024)  // 49 scan blocks
#define PUBF (1 << 30)             // publish flag bit

// ---------------- scratch (device globals; no allocation allowed) ----------
__device__ alignas(16) __nv_bfloat16 g_xsb[NN * FD];  // bf16 features
__device__ alignas(16) float g_as [NN * HH];
__device__ alignas(16) float g_ad [NN * HH];
__device__ alignas(16) float g_h  [NN * FD];
__device__ alignas(16) float g_vd1 [FD * HH];
__device__ alignas(16) float g_vd2 [FD * HH];
__device__ alignas(16) __nv_bfloat16 g_wh1[FD * FD];
__device__ alignas(16) __nv_bfloat16 g_wl1[FD * FD];
__device__ alignas(16) __nv_bfloat16 g_wh2[FD * FD];
__device__ alignas(16) __nv_bfloat16 g_wl2[FD * FD];
// CSR
__device__ int g_deg   [NN];
__device__ int g_rowptr[NN + 1];
__device__ int g_cursor[NN];
__device__ int g_col   [ET];
__device__ int g_pub   [SBLK];

// ====== prep: deg=1 (self loop), pub=0, vd vectors, W transposed hi/lo ======
__global__ void prep(const float* __restrict__ Wd1, const float* __restrict__ ad1,
                     float* __restrict__ vd1,
                     const float* __restrict__ Wd2, const float* __restrict__ ad2,
                     float* __restrict__ vd2,
                     const float* __restrict__ Ws1, const float* __restrict__ Ws2,
                     __nv_bfloat16* __restrict__ wh1, __nv_bfloat16* __restrict__ wl1,
                     __nv_bfloat16* __restrict__ wh2, __nv_bfloat16* __restrict__ wl2,
                     int* __restrict__ deg, int* __restrict__ pub)
{
    int b = blockIdx.x, t = threadIdx.x;
    int i = b * 256 + t;
    if (i < NN) deg[i] = 1;                       // self loop pre-counted
    if (i < SBLK) pub[i] = 0;                     // scan publish slots

    if (b < 128) {
        const float* W = (b < 64) ? Ws1 : Ws2;
        __nv_bfloat16* wh = (b < 64) ? wh1 : wh2;
        __nv_bfloat16* wl = (b < 64) ? wl1 : wl2;
        int idx = (b & 63) * 256 + t;             // 0..16383
        int n = idx >> 7, k = idx & 127;
        float x = W[k * 128 + n];
        __nv_bfloat16 h = __float2bfloat16_rn(x);
        __nv_bfloat16 l = __float2bfloat16_rn(x - __bfloat162float(h));
        wh[n * 128 + k] = h;
        wl[n * 128 + k] = l;
    } else if (b < 130 && t < 128) {
        const float* Wd = (b == 129) ? Wd2 : Wd1;
        const float* ad = (b == 129) ? ad2 : ad1;
        float*       vd = (b == 129) ? vd2 : vd1;
        int k = t;
        #pragma unroll
        for (int h = 0; h < HH; h++) {
            float s = 0.f;
            #pragma unroll 16
            for (int c = 0; c < 64; c++)
                s += Wd[k * 128 + h * 64 + c] * ad[h * 64 + c];
            vd[k * 2 + h] = s;
        }
    }
}

// ======= CSR hist: 4 edges per thread (no return dep -> RED, chains OK) =====
__global__ void csr_hist(const int* __restrict__ ei, int* __restrict__ deg) {
    int t = blockIdx.x * blockDim.x + threadIdx.x;   // t < EE/4
    if (t >= EE / 4) return;
    int d0 = __ldg(ei + EE + 4 * t + 0);
    int d1 = __ldg(ei + EE + 4 * t + 1);
    int d2 = __ldg(ei + EE + 4 * t + 2);
    int d3 = __ldg(ei + EE + 4 * t + 3);
    atomicAdd(&deg[d0], 1);
    atomicAdd(&deg[d1], 1);
    atomicAdd(&deg[d2], 1);
    atomicAdd(&deg[d3], 1);
}

// ======= fused scan: publish block aggregate, spin on predecessors ==========
__global__ void __launch_bounds__(1024) scan_fused(
        const int* __restrict__ deg, int* __restrict__ rowptr,
        int* __restrict__ cursor, int* __restrict__ pub)
{
    __shared__ int sh[1024];
    __shared__ int s_prefix;
    int b = blockIdx.x, t = threadIdx.x;
    int i = b * 1024 + t;
    int v = (i < NN) ? deg[i] : 0;
    sh[t] = v;
    if (t == 0) s_prefix = 0;
    __syncthreads();
    #pragma unroll
    for (int s = 1; s < 1024; s <<= 1) {
        int tmp = (t >= s) ? sh[t - s] : 0;
        __syncthreads();
        sh[t] += tmp;
        __syncthreads();
    }
    if (t == 1023) atomicExch(&pub[b], sh[1023] + PUBF);   // publish aggregate
    if (t < 64 && t < b) {
        int acc = 0;
        for (int p = t; p < b; p += 64) {
            int x;
            do { x = atomicAdd(&pub[p], 0); } while (x < PUBF);
            acc += x - PUBF;
        }
        atomicAdd(&s_prefix, acc);
    }
    __syncthreads();
    int base = s_prefix;
    if (i < NN) {
        int r = base + sh[t] - v;       // exclusive scan + block prefix
        rowptr[i] = r;
        cursor[i] = r + 1;              // slot 0 reserved for self loop
    }
    if (b == 0 && t == 0) rowptr[NN] = ET;
}

// fill: 1 edge/thread (atomic-return chain is latency-critical -> max warps)
__global__ void csr_fill(const int* __restrict__ ei, const int* __restrict__ rowptr,
                         int* __restrict__ cursor, int* __restrict__ col) {
    int t = blockIdx.x * blockDim.x + threadIdx.x;
    if (t < EE) {
        int s = __ldg(ei + t);
        int d = __ldg(ei + EE + t);
        col[atomicAdd(&cursor[d], 1)] = s;
    } else if (t < ET) {
        int n = t - EE;
        col[rowptr[n]] = n;             // self loop at slot 0
    }
}

// ================= tensor-core projection (mma.sync bf16 HMMA) ===============
#define XB_STRIDE 272                 // bytes per padded smem row (136 bf16)
#define SMX  0
#define SWH  34816
#define SWL  69632
#define SATT 104448                   // 128 f32
#define SVD  104960                   // 256 f32
#define SM_DYN 105984

__device__ __forceinline__ void mma16816(float* c, uint32_t a0, uint32_t a1,
                                         uint32_t a2, uint32_t a3,
                                         uint32_t b0, uint32_t b1) {
    asm volatile(
        "mma.sync.aligned.m16n8k16.row.col.f32.bf16.bf16.f32 "
        "{%0,%1,%2,%3}, {%4,%5,%6,%7}, {%8,%9}, {%0,%1,%2,%3};"
        : "+f"(c[0]), "+f"(c[1]), "+f"(c[2]), "+f"(c[3])
        : "r"(a0), "r"(a1), "r"(a2), "r"(a3), "r"(b0), "r"(b1));
}

__global__ void __launch_bounds__(256)
proj_tc(const float* __restrict__ X,
        const __nv_bfloat16* __restrict__ wh, const __nv_bfloat16* __restrict__ wl,
        const float* __restrict__ atts, const float* __restrict__ vd,
        __nv_bfloat16* __restrict__ xsb,
        float* __restrict__ av_s, float* __restrict__ av_d)
{
    extern __shared__ char smem[];
    int tid = threadIdx.x, wid = tid >> 5, lane = tid & 31;
    int base = blockIdx.x * 128;

    if (tid < 128) ((float*)(smem + SATT))[tid] = atts[tid];
    if (tid < 256) ((float*)(smem + SVD))[tid]  = vd[tid];

    for (int i = tid; i < 2048; i += 256) {      // 2048 uint4 per matrix
        int r = i >> 4, c16 = i & 15;
        *(uint4*)(smem + SWH + r * XB_STRIDE + c16 * 16) = ((const uint4*)wh)[i];
        *(uint4*)(smem + SWL + r * XB_STRIDE + c16 * 16) = ((const uint4*)wl)[i];
    }

    {
        const float2* svd2 = (const float2*)(smem + SVD);
        #pragma unroll 1
        for (int k = 0; k < 16; k++) {
            int r = wid + 8 * k;
            int row = base + r;
            float4 xv = make_float4(0.f, 0.f, 0.f, 0.f);
            if (row < NN)
                xv = ((const float4*)(X + (size_t)row * 128))[lane];
            __nv_bfloat162 p0 = __float22bfloat162_rn(make_float2(xv.x, xv.y));
            __nv_bfloat162 p1 = __float22bfloat162_rn(make_float2(xv.z, xv.w));
            uint2 st; st.x = *(unsigned*)&p0; st.y = *(unsigned*)&p1;
            *(uint2*)(smem + SMX + r * XB_STRIDE + lane * 8) = st;
            float2 v0 = svd2[lane * 4 + 0], v1 = svd2[lane * 4 + 1];
            float2 v2 = svd2[lane * 4 + 2], v3 = svd2[lane * 4 + 3];
            float pd0 = xv.x * v0.x + xv.y * v1.x + xv.z * v2.x + xv.w * v3.x;
            float pd1 = xv.x * v0.y + xv.y * v1.y + xv.z * v2.y + xv.w * v3.y;
            #pragma unroll
            for (int o = 16; o; o >>= 1) {
                pd0 += __shfl_xor_sync(0xffffffffu, pd0, o);
                pd1 += __shfl_xor_sync(0xffffffffu, pd1, o);
            }
            if (lane == 0 && row < NN)
                ((float2*)av_d)[row] = make_float2(pd0, pd1);
        }
    }
    __syncthreads();

    float acc[16][4];
    #pragma unroll
    for (int nt = 0; nt < 16; nt++)
        #pragma unroll
        for (int q = 0; q < 4; q++) acc[nt][q] = 0.f;

    int gid = lane >> 2, tig = lane & 3;
    int rowA = wid * 16 + gid;
    const char* sx = smem + SMX;

    #pragma unroll 1
    for (int pass = 0; pass < 2; pass++) {
        const char* sw = smem + (pass ? SWL : SWH);
        #pragma unroll 1
        for (int ks = 0; ks < 8; ks++) {
            int k0 = ks * 16;
            uint32_t a0 = *(const uint32_t*)(sx + rowA * XB_STRIDE + (k0 + 2 * tig) * 2);
            uint32_t a1 = *(const uint32_t*)(sx + (rowA + 8) * XB_STRIDE + (k0 + 2 * tig) * 2);
            uint32_t a2 = *(const uint32_t*)(sx + rowA * XB_STRIDE + (k0 + 8 + 2 * tig) * 2);
            uint32_t a3 = *(const uint32_t*)(sx + (rowA + 8) * XB_STRIDE + (k0 + 8 + 2 * tig) * 2);
            #pragma unroll
            for (int nt = 0; nt < 16; nt++) {
                const char* wr = sw + (nt * 8 + gid) * XB_STRIDE;
                uint32_t b0 = *(const uint32_t*)(wr + (k0 + 2 * tig) * 2);
                uint32_t b1 = *(const uint32_t*)(wr + (k0 + 8 + 2 * tig) * 2);
                mma16816(acc[nt], a0, a1, a2, a3, b0, b1);
            }
        }
    }

    {
        const float* sa = (const float*)(smem + SATT);
        int row0 = base + wid * 16 + gid;
        int row1 = row0 + 8;
        float p0h0 = 0.f, p0h1 = 0.f, p1h0 = 0.f, p1h1 = 0.f;
        #pragma unroll
        for (int nt = 0; nt < 16; nt++) {
            int col = nt * 8 + 2 * tig;
            float s0 = sa[col], s1 = sa[col + 1];
            float d00 = acc[nt][0] * s0 + acc[nt][1] * s1;
            float d01 = acc[nt][2] * s0 + acc[nt][3] * s1;
            if (nt < 8) { p0h0 += d00; p1h0 += d01; }
            else        { p0h1 += d00; p1h1 += d01; }
            __nv_bfloat162 q0 = __float22bfloat162_rn(make_float2(acc[nt][0], acc[nt][1]));
            __nv_bfloat162 q1 = __float22bfloat162_rn(make_float2(acc[nt][2], acc[nt][3]));
            if (row0 < NN) *(unsigned*)(xsb + (size_t)row0 * 128 + col) = *(unsigned*)&q0;
            if (row1 < NN) *(unsigned*)(xsb + (size_t)row1 * 128 + col) = *(unsigned*)&q1;
        }
        #pragma unroll
        for (int o = 1; o <= 2; o <<= 1) {
            p0h0 += __shfl_xor_sync(0xffffffffu, p0h0, o);
            p0h1 += __shfl_xor_sync(0xffffffffu, p0h1, o);
            p1h0 += __shfl_xor_sync(0xffffffffu, p1h0, o);
            p1h1 += __shfl_xor_sync(0xffffffffu, p1h1, o);
        }
        if (tig == 0) {
            if (row0 < NN) ((float2*)av_s)[row0] = make_float2(p0h0, p0h1);
            if (row1 < NN) ((float2*)av_s)[row1] = make_float2(p1h0, p1h1);
        }
    }
}

// ======= fused GAT aggregation: CONVERGENT shfl staging, half-warp gather ====
__global__ void __launch_bounds__(256) gat_agg(
        const int* __restrict__ rowptr, const int* __restrict__ col,
        const float* __restrict__ a_s, const float* __restrict__ a_d,
        const __nv_bfloat16* __restrict__ xsb, const float* __restrict__ b,
        float* __restrict__ out)
{
    int wid = threadIdx.x >> 5, lane = threadIdx.x & 31;
    int n = blockIdx.x * 8 + wid;
    if (n >= NN) return;
    int r0 = rowptr[n], r1 = rowptr[n + 1];
    int deg = r1 - r0;
    float2 adv = ((const float2*)a_d)[n];

    int half = lane >> 4;
    int hl   = lane & 15;
    int h    = hl >> 3;

    float acc[8];
    #pragma unroll
    for (int q = 0; q < 8; q++) acc[q] = 0.f;
    float ws0 = 0.f, ws1 = 0.f;

    for (int base = 0; base < deg; base += 32) {
        int e = base + lane;
        int s = n; float w0 = 0.f, w1 = 0.f;
        if (e < deg) {
            s = __ldg(col + r0 + e);
            float2 av = ((const float2*)a_s)[s];
            float l0 = av.x + adv.x; l0 = l0 > 0.f ? l0 : 0.2f * l0;
            float l1 = av.y + adv.y; l1 = l1 > 0.f ? l1 : 0.2f * l1;
            w0 = __expf(l0); w1 = __expf(l1);
            ws0 += w0; ws1 += w1;
        }
        int cnt = min(32, deg - base);
        int rounds = (cnt + 1) & ~1;           // even: both halves same trips
        #pragma unroll 4
        for (int e2 = half; e2 < rounds; e2 += 2) {
            int   sj  = __shfl_sync(0xffffffffu, s,  e2);
            float w0j = __shfl_sync(0xffffffffu, w0, e2);
            float w1j = __shfl_sync(0xffffffffu, w1, e2);
            float wj  = h ? w1j : w0j;
            uint4 v = ((const uint4*)(xsb + (size_t)sj * 128))[hl];
            __nv_bfloat162* pv = (__nv_bfloat162*)&v;
            #pragma unroll
            for (int q = 0; q < 4; q++) {
                float2 f = __bfloat1622float2(pv[q]);
                acc[2 * q]     += wj * f.x;
                acc[2 * q + 1] += wj * f.y;
            }
        }
    }

    #pragma unroll
    for (int q = 0; q < 8; q++)
        acc[q] += __shfl_xor_sync(0xffffffffu, acc[q], 16);

    #pragma unroll
    for (int off = 16; off; off >>= 1) {
        ws0 += __shfl_xor_sync(0xffffffffu, ws0, off);
        ws1 += __shfl_xor_sync(0xffffffffu, ws1, off);
    }
    float inv = 1.f / (h ? ws1 : ws0);

    if (half == 0) {
        float4 b0 = ((const float4*)b)[hl * 2];
        float4 b1 = ((const float4*)b)[hl * 2 + 1];
        float4 o0, o1;
        o0.x = fmaxf(acc[0] * inv + b0.x, 0.f);
        o0.y = fmaxf(acc[1] * inv + b0.y, 0.f);
        o0.z = fmaxf(acc[2] * inv + b0.z, 0.f);
        o0.w = fmaxf(acc[3] * inv + b0.w, 0.f);
        o1.x = fmaxf(acc[4] * inv + b1.x, 0.f);
        o1.y = fmaxf(acc[5] * inv + b1.y, 0.f);
        o1.z = fmaxf(acc[6] * inv + b1.z, 0.f);
        o1.w = fmaxf(acc[7] * inv + b1.w, 0.f);
        ((float4*)(out + (size_t)n * 128))[hl * 2]     = o0;
        ((float4*)(out + (size_t)n * 128))[hl * 2 + 1] = o1;
    }
}

// ================= fused pooling + final linear (batch is SORTED) ============
__global__ void __launch_bounds__(256) pool_final(
        const float* __restrict__ h, const int* __restrict__ batch,
        const float* __restrict__ Wl, const float* __restrict__ bl,
        float* __restrict__ out)
{
    __shared__ float part[256];
    __shared__ float row[128];
    int g = blockIdx.x;

    int a = 0, bnd = NN;
    while (a < bnd) { int m = (a + bnd) >> 1; if (batch[m] < g) a = m + 1; else bnd = m; }
    int lo = a;
    a = lo; bnd = NN;
    while (a < bnd) { int m = (a + bnd) >> 1; if (batch[m] < g + 1) a = m + 1; else bnd = m; }
    int hi = a;

    int c    = threadIdx.x & 127;
    int half = threadIdx.x >> 7;
    float acc = 0.f;
    for (int r = lo + half; r < hi; r += 2)
        acc += h[(size_t)r * 128 + c];
    part[threadIdx.x] = acc;
    __syncthreads();
    if (threadIdx.x < 128) {
        float inv = 1.f / fmaxf((float)(hi - lo), 1.f);
        row[threadIdx.x] = (part[threadIdx.x] + part[threadIdx.x + 128]) * inv;
    }
    __syncthreads();
    if (threadIdx.x < OUTD) {
        float s = bl[threadIdx.x];
        #pragma unroll 16
        for (int j = 0; j < 128; j++)
            s += row[j] * Wl[j * OUTD + threadIdx.x];
        out[g * OUTD + threadIdx.x] = s;
    }
}

// ================= launch =====================================================
extern "C" void kernel_launch(void* const* d_in, const int* in_sizes, int n_in,
                              void* d_out, int out_size)
{
    const float* x     = (const float*)d_in[0];
    const int*   ei    = (const int*)  d_in[1];
    const int*   batch = (const int*)  d_in[2];
    const float* Ws1   = (const float*)d_in[3];
    const float* Wd1   = (const float*)d_in[4];
    const float* as1   = (const float*)d_in[5];
    const float* ad1   = (const float*)d_in[6];
    const float* b1    = (const float*)d_in[7];
    const float* Ws2   = (const float*)d_in[8];
    const float* Wd2   = (const float*)d_in[9];
    const float* as2   = (const float*)d_in[10];
    const float* ad2   = (const float*)d_in[11];
    const float* b2    = (const float*)d_in[12];
    const float* Wl    = (const float*)d_in[13];
    const float* bl    = (const float*)d_in[14];
    float* out = (float*)d_out;

    void *p_xsb, *p_as, *p_ad, *p_h, *p_vd1, *p_vd2;
    void *p_wh1, *p_wl1, *p_wh2, *p_wl2;
    void *p_deg, *p_rowptr, *p_cursor, *p_col, *p_pub;
    cudaGetSymbolAddress(&p_xsb, g_xsb);
    cudaGetSymbolAddress(&p_as,  g_as);
    cudaGetSymbolAddress(&p_ad,  g_ad);
    cudaGetSymbolAddress(&p_h,   g_h);
    cudaGetSymbolAddress(&p_vd1, g_vd1);
    cudaGetSymbolAddress(&p_vd2, g_vd2);
    cudaGetSymbolAddress(&p_wh1, g_wh1);
    cudaGetSymbolAddress(&p_wl1, g_wl1);
    cudaGetSymbolAddress(&p_wh2, g_wh2);
    cudaGetSymbolAddress(&p_wl2, g_wl2);
    cudaGetSymbolAddress(&p_deg,    g_deg);
    cudaGetSymbolAddress(&p_rowptr, g_rowptr);
    cudaGetSymbolAddress(&p_cursor, g_cursor);
    cudaGetSymbolAddress(&p_col,    g_col);
    cudaGetSymbolAddress(&p_pub,    g_pub);

    __nv_bfloat16* xsb = (__nv_bfloat16*)p_xsb;
    float* asv = (float*)p_as;  float* adv = (float*)p_ad;
    float* hbuf= (float*)p_h;
    float* vd1 = (float*)p_vd1; float* vd2 = (float*)p_vd2;
    __nv_bfloat16* wh1 = (__nv_bfloat16*)p_wh1;
    __nv_bfloat16* wl1 = (__nv_bfloat16*)p_wl1;
    __nv_bfloat16* wh2 = (__nv_bfloat16*)p_wh2;
    __nv_bfloat16* wl2 = (__nv_bfloat16*)p_wl2;
    int* deg    = (int*)p_deg;    int* rowptr = (int*)p_rowptr;
    int* cursor = (int*)p_cursor; int* col    = (int*)p_col;
    int* pub    = (int*)p_pub;

    const int AGG_GRID  = (NN + 7) / 8;
    const int NODE_GRID = (NN + 255) / 256;
    const int HIST_GRID = (EE / 4 + 255) / 256;
    const int FILL_GRID = (ET + 255) / 256;

    cudaFuncSetAttribute(proj_tc, cudaFuncAttributeMaxDynamicSharedMemorySize, SM_DYN);

    prep<<<NODE_GRID, 256>>>(Wd1, ad1, vd1, Wd2, ad2, vd2,
                             Ws1, Ws2, wh1, wl1, wh2, wl2, deg, pub);

    csr_hist<<<HIST_GRID, 256>>>(ei, deg);
    scan_fused<<<SBLK, 1024>>>(deg, rowptr, cursor, pub);
    csr_fill<<<FILL_GRID, 256>>>(ei, rowptr, cursor, col);

    proj_tc<<<NTILE, 256, SM_DYN>>>(x, wh1, wl1, as1, vd1, xsb, asv, adv);
    gat_agg<<<AGG_GRID, 256>>>(rowptr, col, asv, adv, xsb, b1, hbuf);

    proj_tc<<<NTILE, 256, SM_DYN>>>(hbuf, wh2, wl2, as2, vd2, xsb, asv, adv);
    gat_agg<<<AGG_GRID, 256>>>(rowptr, col, asv, adv, xsb, b2, hbuf);

    pool_final<<<GG, 256>>>(hbuf, batch, Wl, bl, out);
}

// round 16
// speedup vs baseline: 1.4336x; 1.4336x over previous
#include <cuda_runtime.h>
#include <cuda_bf16.h>
#include <cstdint>

#define NN   50000
#define EE   800000
#define ET   (EE + NN)        // edges incl. self loops = 850000
#define FD   128
#define HH   2
#define GG   64
#define OUTD 10
#define NTILE ((NN + 127) / 128)   // 391 M-tiles
#define SBLK ((NN + 1023) / 1024)  // 49 scan blocks
#define PUBF (1 << 30)             // publish flag bit

// ---------------- scratch (device globals; no allocation allowed) ----------
__device__ alignas(16) __nv_bfloat16 g_xsb[NN * FD];  // bf16 features
__device__ alignas(16) float g_as [NN * HH];
__device__ alignas(16) float g_ad [NN * HH];
__device__ alignas(16) float g_h  [NN * FD];
__device__ alignas(16) float g_vd1 [FD * HH];
__device__ alignas(16) float g_vd2 [FD * HH];
__device__ alignas(16) __nv_bfloat16 g_wh1[FD * FD];
__device__ alignas(16) __nv_bfloat16 g_wl1[FD * FD];
__device__ alignas(16) __nv_bfloat16 g_wh2[FD * FD];
__device__ alignas(16) __nv_bfloat16 g_wl2[FD * FD];
// CSR
__device__ int g_deg   [NN];
__device__ int g_rowptr[NN + 1];
__device__ int g_cursor[NN];
__device__ int g_col   [ET];
__device__ int g_pub   [SBLK];

// ====== prep: deg=1 (self loop), pub=0, vd vectors, W transposed hi/lo ======
__global__ void prep(const float* __restrict__ Wd1, const float* __restrict__ ad1,
                     float* __restrict__ vd1,
                     const float* __restrict__ Wd2, const float* __restrict__ ad2,
                     float* __restrict__ vd2,
                     const float* __restrict__ Ws1, const float* __restrict__ Ws2,
                     __nv_bfloat16* __restrict__ wh1, __nv_bfloat16* __restrict__ wl1,
                     __nv_bfloat16* __restrict__ wh2, __nv_bfloat16* __restrict__ wl2,
                     int* __restrict__ deg, int* __restrict__ pub)
{
    int b = blockIdx.x, t = threadIdx.x;
    int i = b * 256 + t;
    if (i < NN) deg[i] = 1;                       // self loop pre-counted
    if (i < SBLK) pub[i] = 0;                     // scan publish slots

    if (b < 128) {
        const float* W = (b < 64) ? Ws1 : Ws2;
        __nv_bfloat16* wh = (b < 64) ? wh1 : wh2;
        __nv_bfloat16* wl = (b < 64) ? wl1 : wl2;
        int idx = (b & 63) * 256 + t;             // 0..16383
        int n = idx >> 7, k = idx & 127;
        float x = W[k * 128 + n];
        __nv_bfloat16 h = __float2bfloat16_rn(x);
        __nv_bfloat16 l = __float2bfloat16_rn(x - __bfloat162float(h));
        wh[n * 128 + k] = h;
        wl[n * 128 + k] = l;
    } else if (b < 130 && t < 128) {
        const float* Wd = (b == 129) ? Wd2 : Wd1;
        const float* ad = (b == 129) ? ad2 : ad1;
        float*       vd = (b == 129) ? vd2 : vd1;
        int k = t;
        #pragma unroll
        for (int h = 0; h < HH; h++) {
            float s = 0.f;
            #pragma unroll 16
            for (int c = 0; c < 64; c++)
                s += Wd[k * 128 + h * 64 + c] * ad[h * 64 + c];
            vd[k * 2 + h] = s;
        }
    }
}

// ======= CSR hist: 4 edges per thread (no return dep -> RED, chains OK) =====
__global__ void csr_hist(const int* __restrict__ ei, int* __restrict__ deg) {
    int t = blockIdx.x * blockDim.x + threadIdx.x;   // t < EE/4
    if (t >= EE / 4) return;
    int d0 = __ldg(ei + EE + 4 * t + 0);
    int d1 = __ldg(ei + EE + 4 * t + 1);
    int d2 = __ldg(ei + EE + 4 * t + 2);
    int d3 = __ldg(ei + EE + 4 * t + 3);
    atomicAdd(&deg[d0], 1);
    atomicAdd(&deg[d1], 1);
    atomicAdd(&deg[d2], 1);
    atomicAdd(&deg[d3], 1);
}

// ======= fused scan: publish block aggregate, spin on predecessors ==========
__global__ void __launch_bounds__(1024) scan_fused(
        const int* __restrict__ deg, int* __restrict__ rowptr,
        int* __restrict__ cursor, int* __restrict__ pub)
{
    __shared__ int sh[1024];
    __shared__ int s_prefix;
    int b = blockIdx.x, t = threadIdx.x;
    int i = b * 1024 + t;
    int v = (i < NN) ? deg[i] : 0;
    sh[t] = v;
    if (t == 0) s_prefix = 0;
    __syncthreads();
    #pragma unroll
    for (int s = 1; s < 1024; s <<= 1) {
        int tmp = (t >= s) ? sh[t - s] : 0;
        __syncthreads();
        sh[t] += tmp;
        __syncthreads();
    }
    if (t == 1023) atomicExch(&pub[b], sh[1023] + PUBF);   // publish aggregate
    if (t < 64 && t < b) {
        int acc = 0;
        for (int p = t; p < b; p += 64) {
            int x;
            do { x = atomicAdd(&pub[p], 0); } while (x < PUBF);
            acc += x - PUBF;
        }
        atomicAdd(&s_prefix, acc);
    }
    __syncthreads();
    int base = s_prefix;
    if (i < NN) {
        int r = base + sh[t] - v;       // exclusive scan + block prefix
        rowptr[i] = r;
        cursor[i] = r + 1;              // slot 0 reserved for self loop
    }
    if (b == 0 && t == 0) rowptr[NN] = ET;
}

// fill: 1 edge/thread (atomic-return chain is latency-critical -> max warps)
__global__ void csr_fill(const int* __restrict__ ei, const int* __restrict__ rowptr,
                         int* __restrict__ cursor, int* __restrict__ col) {
    int t = blockIdx.x * blockDim.x + threadIdx.x;
    if (t < EE) {
        int s = __ldg(ei + t);
        int d = __ldg(ei + EE + t);
        col[atomicAdd(&cursor[d], 1)] = s;
    } else if (t < ET) {
        int n = t - EE;
        col[rowptr[n]] = n;             // self loop at slot 0
    }
}

// ================= tensor-core projection (mma.sync bf16 HMMA) ===============
#define XB_STRIDE 272                 // bytes per padded smem row (136 bf16)
#define SMX  0
#define SWH  34816
#define SWL  69632
#define SATT 104448                   // 128 f32
#define SVD  104960                   // 256 f32
#define SM_DYN 105984

__device__ __forceinline__ void mma16816(float* c, uint32_t a0, uint32_t a1,
                                         uint32_t a2, uint32_t a3,
                                         uint32_t b0, uint32_t b1) {
    asm volatile(
        "mma.sync.aligned.m16n8k16.row.col.f32.bf16.bf16.f32 "
        "{%0,%1,%2,%3}, {%4,%5,%6,%7}, {%8,%9}, {%0,%1,%2,%3};"
        : "+f"(c[0]), "+f"(c[1]), "+f"(c[2]), "+f"(c[3])
        : "r"(a0), "r"(a1), "r"(a2), "r"(a3), "r"(b0), "r"(b1));
}

__global__ void __launch_bounds__(256)
proj_tc(const float* __restrict__ X,
        const __nv_bfloat16* __restrict__ wh, const __nv_bfloat16* __restrict__ wl,
        const float* __restrict__ atts, const float* __restrict__ vd,
        __nv_bfloat16* __restrict__ xsb,
        float* __restrict__ av_s, float* __restrict__ av_d)
{
    extern __shared__ char smem[];
    int tid = threadIdx.x, wid = tid >> 5, lane = tid & 31;
    int base = blockIdx.x * 128;

    if (tid < 128) ((float*)(smem + SATT))[tid] = atts[tid];
    if (tid < 256) ((float*)(smem + SVD))[tid]  = vd[tid];

    for (int i = tid; i < 2048; i += 256) {      // 2048 uint4 per matrix
        int r = i >> 4, c16 = i & 15;
        *(uint4*)(smem + SWH + r * XB_STRIDE + c16 * 16) = ((const uint4*)wh)[i];
        *(uint4*)(smem + SWL + r * XB_STRIDE + c16 * 16) = ((const uint4*)wl)[i];
    }

    {
        const float2* svd2 = (const float2*)(smem + SVD);
        #pragma unroll 1
        for (int k = 0; k < 16; k++) {
            int r = wid + 8 * k;
            int row = base + r;
            float4 xv = make_float4(0.f, 0.f, 0.f, 0.f);
            if (row < NN)
                xv = ((const float4*)(X + (size_t)row * 128))[lane];
            __nv_bfloat162 p0 = __float22bfloat162_rn(make_float2(xv.x, xv.y));
            __nv_bfloat162 p1 = __float22bfloat162_rn(make_float2(xv.z, xv.w));
            uint2 st; st.x = *(unsigned*)&p0; st.y = *(unsigned*)&p1;
            *(uint2*)(smem + SMX + r * XB_STRIDE + lane * 8) = st;
            float2 v0 = svd2[lane * 4 + 0], v1 = svd2[lane * 4 + 1];
            float2 v2 = svd2[lane * 4 + 2], v3 = svd2[lane * 4 + 3];
            float pd0 = xv.x * v0.x + xv.y * v1.x + xv.z * v2.x + xv.w * v3.x;
            float pd1 = xv.x * v0.y + xv.y * v1.y + xv.z * v2.y + xv.w * v3.y;
            #pragma unroll
            for (int o = 16; o; o >>= 1) {
                pd0 += __shfl_xor_sync(0xffffffffu, pd0, o);
                pd1 += __shfl_xor_sync(0xffffffffu, pd1, o);
            }
            if (lane == 0 && row < NN)
                ((float2*)av_d)[row] = make_float2(pd0, pd1);
        }
    }
    __syncthreads();

    float acc[16][4];
    #pragma unroll
    for (int nt = 0; nt < 16; nt++)
        #pragma unroll
        for (int q = 0; q < 4; q++) acc[nt][q] = 0.f;

    int gid = lane >> 2, tig = lane & 3;
    int rowA = wid * 16 + gid;
    const char* sx = smem + SMX;

    #pragma unroll 1
    for (int pass = 0; pass < 2; pass++) {
        const char* sw = smem + (pass ? SWL : SWH);
        #pragma unroll 1
        for (int ks = 0; ks < 8; ks++) {
            int k0 = ks * 16;
            uint32_t a0 = *(const uint32_t*)(sx + rowA * XB_STRIDE + (k0 + 2 * tig) * 2);
            uint32_t a1 = *(const uint32_t*)(sx + (rowA + 8) * XB_STRIDE + (k0 + 2 * tig) * 2);
            uint32_t a2 = *(const uint32_t*)(sx + rowA * XB_STRIDE + (k0 + 8 + 2 * tig) * 2);
            uint32_t a3 = *(const uint32_t*)(sx + (rowA + 8) * XB_STRIDE + (k0 + 8 + 2 * tig) * 2);
            #pragma unroll
            for (int nt = 0; nt < 16; nt++) {
                const char* wr = sw + (nt * 8 + gid) * XB_STRIDE;
                uint32_t b0 = *(const uint32_t*)(wr + (k0 + 2 * tig) * 2);
                uint32_t b1 = *(const uint32_t*)(wr + (k0 + 8 + 2 * tig) * 2);
                mma16816(acc[nt], a0, a1, a2, a3, b0, b1);
            }
        }
    }

    {
        const float* sa = (const float*)(smem + SATT);
        int row0 = base + wid * 16 + gid;
        int row1 = row0 + 8;
        float p0h0 = 0.f, p0h1 = 0.f, p1h0 = 0.f, p1h1 = 0.f;
        #pragma unroll
        for (int nt = 0; nt < 16; nt++) {
            int col = nt * 8 + 2 * tig;
            float s0 = sa[col], s1 = sa[col + 1];
            float d00 = acc[nt][0] * s0 + acc[nt][1] * s1;
            float d01 = acc[nt][2] * s0 + acc[nt][3] * s1;
            if (nt < 8) { p0h0 += d00; p1h0 += d01; }
            else        { p0h1 += d00; p1h1 += d01; }
            __nv_bfloat162 q0 = __float22bfloat162_rn(make_float2(acc[nt][0], acc[nt][1]));
            __nv_bfloat162 q1 = __float22bfloat162_rn(make_float2(acc[nt][2], acc[nt][3]));
            if (row0 < NN) *(unsigned*)(xsb + (size_t)row0 * 128 + col) = *(unsigned*)&q0;
            if (row1 < NN) *(unsigned*)(xsb + (size_t)row1 * 128 + col) = *(unsigned*)&q1;
        }
        #pragma unroll
        for (int o = 1; o <= 2; o <<= 1) {
            p0h0 += __shfl_xor_sync(0xffffffffu, p0h0, o);
            p0h1 += __shfl_xor_sync(0xffffffffu, p0h1, o);
            p1h0 += __shfl_xor_sync(0xffffffffu, p1h0, o);
            p1h1 += __shfl_xor_sync(0xffffffffu, p1h1, o);
        }
        if (tig == 0) {
            if (row0 < NN) ((float2*)av_s)[row0] = make_float2(p0h0, p0h1);
            if (row1 < NN) ((float2*)av_s)[row1] = make_float2(p1h0, p1h1);
        }
    }
}

// ======= fused GAT aggregation: CONVERGENT shfl staging, half-warp gather ====
__global__ void __launch_bounds__(256) gat_agg(
        const int* __restrict__ rowptr, const int* __restrict__ col,
        const float* __restrict__ a_s, const float* __restrict__ a_d,
        const __nv_bfloat16* __restrict__ xsb, const float* __restrict__ b,
        float* __restrict__ out)
{
    int wid = threadIdx.x >> 5, lane = threadIdx.x & 31;
    int n = blockIdx.x * 8 + wid;
    if (n >= NN) return;
    int r0 = rowptr[n], r1 = rowptr[n + 1];
    int deg = r1 - r0;
    float2 adv = ((const float2*)a_d)[n];

    int half = lane >> 4;
    int hl   = lane & 15;
    int h    = hl >> 3;

    float acc[8];
    #pragma unroll
    for (int q = 0; q < 8; q++) acc[q] = 0.f;
    float ws0 = 0.f, ws1 = 0.f;

    for (int base = 0; base < deg; base += 32) {
        int e = base + lane;
        int s = n; float w0 = 0.f, w1 = 0.f;
        if (e < deg) {
            s = __ldg(col + r0 + e);
            float2 av = ((const float2*)a_s)[s];
            float l0 = av.x + adv.x; l0 = l0 > 0.f ? l0 : 0.2f * l0;
            float l1 = av.y + adv.y; l1 = l1 > 0.f ? l1 : 0.2f * l1;
            w0 = __expf(l0); w1 = __expf(l1);
            ws0 += w0; ws1 += w1;
        }
        int cnt = min(32, deg - base);
        int rounds = (cnt + 1) & ~1;           // even: both halves same trips
        #pragma unroll 4
        for (int e2 = half; e2 < rounds; e2 += 2) {
            int   sj  = __shfl_sync(0xffffffffu, s,  e2);
            float w0j = __shfl_sync(0xffffffffu, w0, e2);
            float w1j = __shfl_sync(0xffffffffu, w1, e2);
            float wj  = h ? w1j : w0j;
            uint4 v = ((const uint4*)(xsb + (size_t)sj * 128))[hl];
            __nv_bfloat162* pv = (__nv_bfloat162*)&v;
            #pragma unroll
            for (int q = 0; q < 4; q++) {
                float2 f = __bfloat1622float2(pv[q]);
                acc[2 * q]     += wj * f.x;
                acc[2 * q + 1] += wj * f.y;
            }
        }
    }

    #pragma unroll
    for (int q = 0; q < 8; q++)
        acc[q] += __shfl_xor_sync(0xffffffffu, acc[q], 16);

    #pragma unroll
    for (int off = 16; off; off >>= 1) {
        ws0 += __shfl_xor_sync(0xffffffffu, ws0, off);
        ws1 += __shfl_xor_sync(0xffffffffu, ws1, off);
    }
    float inv = 1.f / (h ? ws1 : ws0);

    if (half == 0) {
        float4 b0 = ((const float4*)b)[hl * 2];
        float4 b1 = ((const float4*)b)[hl * 2 + 1];
        float4 o0, o1;
        o0.x = fmaxf(acc[0] * inv + b0.x, 0.f);
        o0.y = fmaxf(acc[1] * inv + b0.y, 0.f);
        o0.z = fmaxf(acc[2] * inv + b0.z, 0.f);
        o0.w = fmaxf(acc[3] * inv + b0.w, 0.f);
        o1.x = fmaxf(acc[4] * inv + b1.x, 0.f);
        o1.y = fmaxf(acc[5] * inv + b1.y, 0.f);
        o1.z = fmaxf(acc[6] * inv + b1.z, 0.f);
        o1.w = fmaxf(acc[7] * inv + b1.w, 0.f);
        ((float4*)(out + (size_t)n * 128))[hl * 2]     = o0;
        ((float4*)(out + (size_t)n * 128))[hl * 2 + 1] = o1;
    }
}

// ================= fused pooling + final linear (batch is SORTED) ============
__global__ void __launch_bounds__(256) pool_final(
        const float* __restrict__ h, const int* __restrict__ batch,
        const float* __restrict__ Wl, const float* __restrict__ bl,
        float* __restrict__ out)
{
    __shared__ float part[256];
    __shared__ float row[128];
    int g = blockIdx.x;

    int a = 0, bnd = NN;
    while (a < bnd) { int m = (a + bnd) >> 1; if (batch[m] < g) a = m + 1; else bnd = m; }
    int lo = a;
    a = lo; bnd = NN;
    while (a < bnd) { int m = (a + bnd) >> 1; if (batch[m] < g + 1) a = m + 1; else bnd = m; }
    int hi = a;

    int c    = threadIdx.x & 127;
    int half = threadIdx.x >> 7;
    float acc = 0.f;
    for (int r = lo + half; r < hi; r += 2)
        acc += h[(size_t)r * 128 + c];
    part[threadIdx.x] = acc;
    __syncthreads();
    if (threadIdx.x < 128) {
        float inv = 1.f / fmaxf((float)(hi - lo), 1.f);
        row[threadIdx.x] = (part[threadIdx.x] + part[threadIdx.x + 128]) * inv;
    }
    __syncthreads();
    if (threadIdx.x < OUTD) {
        float s = bl[threadIdx.x];
        #pragma unroll 16
        for (int j = 0; j < 128; j++)
            s += row[j] * Wl[j * OUTD + threadIdx.x];
        out[g * OUTD + threadIdx.x] = s;
    }
}

// ================= launch =====================================================
extern "C" void kernel_launch(void* const* d_in, const int* in_sizes, int n_in,
                              void* d_out, int out_size)
{
    const float* x     = (const float*)d_in[0];
    const int*   ei    = (const int*)  d_in[1];
    const int*   batch = (const int*)  d_in[2];
    const float* Ws1   = (const float*)d_in[3];
    const float* Wd1   = (const float*)d_in[4];
    const float* as1   = (const float*)d_in[5];
    const float* ad1   = (const float*)d_in[6];
    const float* b1    = (const float*)d_in[7];
    const float* Ws2   = (const float*)d_in[8];
    const float* Wd2   = (const float*)d_in[9];
    const float* as2   = (const float*)d_in[10];
    const float* ad2   = (const float*)d_in[11];
    const float* b2    = (const float*)d_in[12];
    const float* Wl    = (const float*)d_in[13];
    const float* bl    = (const float*)d_in[14];
    float* out = (float*)d_out;

    void *p_xsb, *p_as, *p_ad, *p_h, *p_vd1, *p_vd2;
    void *p_wh1, *p_wl1, *p_wh2, *p_wl2;
    void *p_deg, *p_rowptr, *p_cursor, *p_col, *p_pub;
    cudaGetSymbolAddress(&p_xsb, g_xsb);
    cudaGetSymbolAddress(&p_as,  g_as);
    cudaGetSymbolAddress(&p_ad,  g_ad);
    cudaGetSymbolAddress(&p_h,   g_h);
    cudaGetSymbolAddress(&p_vd1, g_vd1);
    cudaGetSymbolAddress(&p_vd2, g_vd2);
    cudaGetSymbolAddress(&p_wh1, g_wh1);
    cudaGetSymbolAddress(&p_wl1, g_wl1);
    cudaGetSymbolAddress(&p_wh2, g_wh2);
    cudaGetSymbolAddress(&p_wl2, g_wl2);
    cudaGetSymbolAddress(&p_deg,    g_deg);
    cudaGetSymbolAddress(&p_rowptr, g_rowptr);
    cudaGetSymbolAddress(&p_cursor, g_cursor);
    cudaGetSymbolAddress(&p_col,    g_col);
    cudaGetSymbolAddress(&p_pub,    g_pub);

    __nv_bfloat16* xsb = (__nv_bfloat16*)p_xsb;
    float* asv = (float*)p_as;  float* adv = (float*)p_ad;
    float* hbuf= (float*)p_h;
    float* vd1 = (float*)p_vd1; float* vd2 = (float*)p_vd2;
    __nv_bfloat16* wh1 = (__nv_bfloat16*)p_wh1;
    __nv_bfloat16* wl1 = (__nv_bfloat16*)p_wl1;
    __nv_bfloat16* wh2 = (__nv_bfloat16*)p_wh2;
    __nv_bfloat16* wl2 = (__nv_bfloat16*)p_wl2;
    int* deg    = (int*)p_deg;    int* rowptr = (int*)p_rowptr;
    int* cursor = (int*)p_cursor; int* col    = (int*)p_col;
    int* pub    = (int*)p_pub;

    const int AGG_GRID  = (NN + 7) / 8;
    const int NODE_GRID = (NN + 255) / 256;
    const int HIST_GRID = (EE / 4 + 255) / 256;
    const int FILL_GRID = (ET + 255) / 256;

    cudaFuncSetAttribute(proj_tc, cudaFuncAttributeMaxDynamicSharedMemorySize, SM_DYN);

    prep<<<NODE_GRID, 256>>>(Wd1, ad1, vd1, Wd2, ad2, vd2,
                             Ws1, Ws2, wh1, wl1, wh2, wl2, deg, pub);

    csr_hist<<<HIST_GRID, 256>>>(ei, deg);
    scan_fused<<<SBLK, 1024>>>(deg, rowptr, cursor, pub);
    csr_fill<<<FILL_GRID, 256>>>(ei, rowptr, cursor, col);

    proj_tc<<<NTILE, 256, SM_DYN>>>(x, wh1, wl1, as1, vd1, xsb, asv, adv);
    gat_agg<<<AGG_GRID, 256>>>(rowptr, col, asv, adv, xsb, b1, hbuf);

    proj_tc<<<NTILE, 256, SM_DYN>>>(hbuf, wh2, wl2, as2, vd2, xsb, asv, adv);
    gat_agg<<<AGG_GRID, 256>>>(rowptr, col, asv, adv, xsb, b2, hbuf);

    pool_final<<<GG, 256>>>(hbuf, batch, Wl, bl, out);
}